// round 15
// baseline (speedup 1.0000x reference)
#include <cuda_runtime.h>
#include <cuda_fp16.h>
#include <cstdint>

#define BB 2
#define TT 4096
#define CC 768
#define HH 12
#define DK 64
#define M_TOK (BB*TT)      // 8192
#define N_QKV (3*CC)       // 2304

// attn fp16 tiles: 64 rows x 72-half pitch, TRIPLE buffered
#define HPITCH 72
#define TILE_H (64*HPITCH)
#define BUF_H  (2*TILE_H)             // K + Vt per buffer (9216 halves)
#define ATTN_SMEM (3*BUF_H*2)         // 55296 bytes

// fp16 GEMM smem (qkv, 128x128): 2 planes x 128 rows x 40-half pitch, K-chunk 32, triple
#define GP1 40
#define PLANE1 (128*GP1)              // 5120 halves
#define GBUF1  (2*PLANE1)             // 10240 halves per buffer
#define GEMM_SMEM (3*GBUF1*2)         // 61440 bytes

// proj GEMM smem (64x128 tiles): A 64 rows + B 128 rows
#define PLANE_A64 (64*GP1)            // 2560 halves
#define GBUF64 (PLANE_A64 + PLANE1)   // 7680 halves per buffer
#define GEMM64_SMEM (3*GBUF64*2)      // 46080 bytes

// V-transpose staging pitch (halves): 136 -> 272B rows, 16B-aligned uint4 reads
#define VTP 136

// K pre-scale: (1/8) * log2(e)
#define KSCALE 0.180336879f

// Scratch (allocation-free rule: __device__ globals)
__device__ __half g_qh [(size_t)BB*HH*TT*DK];
__device__ __half g_k  [(size_t)BB*HH*TT*DK];
__device__ __half g_vt [(size_t)BB*HH*DK*TT];
__device__ __half g_ah [(size_t)BB*TT*CC];
__device__ __half g_xh [(size_t)M_TOK*CC];
__device__ __half g_wqh[(size_t)N_QKV*CC];
__device__ __half g_woh[(size_t)CC*CC];

__device__ __forceinline__ uint32_t packh2(float lo, float hi) {
    __half2 h = __floats2half2_rn(lo, hi);
    return *(uint32_t*)&h;
}

__device__ __forceinline__ void mma_f16(float c[4],
                                        uint32_t a0, uint32_t a1, uint32_t a2, uint32_t a3,
                                        uint32_t b0, uint32_t b1) {
    asm volatile(
        "mma.sync.aligned.m16n8k16.row.col.f32.f16.f16.f32 "
        "{%0,%1,%2,%3}, {%4,%5,%6,%7}, {%8,%9}, {%0,%1,%2,%3};"
        : "+f"(c[0]), "+f"(c[1]), "+f"(c[2]), "+f"(c[3])
        : "r"(a0), "r"(a1), "r"(a2), "r"(a3), "r"(b0), "r"(b1));
}

__device__ __forceinline__ void ldsm4(uint32_t r[4], uint32_t saddr) {
    asm volatile("ldmatrix.sync.aligned.m8n8.x4.shared.b16 {%0,%1,%2,%3}, [%4];"
        : "=r"(r[0]), "=r"(r[1]), "=r"(r[2]), "=r"(r[3]) : "r"(saddr));
}

__device__ __forceinline__ void cp16(void* dst_smem, const void* src) {
    uint32_t d = (uint32_t)__cvta_generic_to_shared(dst_smem);
    asm volatile("cp.async.cg.shared.global [%0], [%1], 16;" :: "r"(d), "l"(src));
}
__device__ __forceinline__ void cp_commit() {
    asm volatile("cp.async.commit_group;");
}
__device__ __forceinline__ void cp_wait1() { asm volatile("cp.async.wait_group 1;"); }
__device__ __forceinline__ void cp_wait0() { asm volatile("cp.async.wait_group 0;"); }

// ---------------------------------------------------------------------------
// Merged prepass: block-range dispatch.
// ---------------------------------------------------------------------------
#define XB (M_TOK*CC/1024)        // 6144
#define QB ((N_QKV/32)*(CC/32))   // 1728
#define OB ((CC/32)*(CC/32))      // 576

__global__ __launch_bounds__(256) void prepass_kernel(
    const float* __restrict__ x,
    const float* __restrict__ Wq,
    const float* __restrict__ Wo)
{
    __shared__ float ts[32][33];
    const int b   = blockIdx.x;
    const int tid = threadIdx.x;

    if (b < XB) {
        size_t base = ((size_t)b * 256 + tid) * 4;
        float4 v = *(const float4*)(x + base);
        *(__half2*)(g_xh + base)     = __floats2half2_rn(v.x, v.y);
        *(__half2*)(g_xh + base + 2) = __floats2half2_rn(v.z, v.w);
        return;
    }

    const float* W;
    __half* T;
    int K, N, bx, by;
    if (b < XB + QB) {
        int bb2 = b - XB;
        W = Wq; T = g_wqh; K = CC; N = N_QKV;
        bx = bb2 % (N_QKV / 32); by = bb2 / (N_QKV / 32);
    } else {
        int bb2 = b - XB - QB;
        W = Wo; T = g_woh; K = CC; N = CC;
        bx = bb2 % (CC / 32); by = bb2 / (CC / 32);
    }
    const int tx = tid & 31, ty = tid >> 5;           // 32 x 8
    const int n0 = bx * 32, k0 = by * 32;
#pragma unroll
    for (int i = 0; i < 32; i += 8)
        ts[ty + i][tx] = W[(size_t)(k0 + ty + i) * N + n0 + tx];
    __syncthreads();
#pragma unroll
    for (int i = 0; i < 32; i += 8)
        T[(size_t)(n0 + ty + i) * K + k0 + tx] = __float2half_rn(ts[tx][ty + i]);
}

// ===========================================================================
// fp16 GEMM core #1: C[128x128], 8 warps (4m x 2n), K-chunk 32,
// triple-buffered, distance-2 prefetch issued right after the barrier.
// ===========================================================================
struct GemmFrag {
    float c[2][8][4];
};

__device__ __forceinline__ void gemm1_tile(
    GemmFrag& F,
    const __half* __restrict__ A, const __half* __restrict__ B,
    int Ksz, __half* sdyn, int m_base, int n_base)
{
    const int tid  = threadIdx.x;
    const int lane = tid & 31;
#pragma unroll
    for (int mt = 0; mt < 2; mt++)
#pragma unroll
        for (int nb = 0; nb < 8; nb++)
#pragma unroll
            for (int j = 0; j < 4; j++) F.c[mt][nb][j] = 0.0f;

    const int s_row  = tid >> 2;
    const int s_col8 = (tid & 3) << 3;

    auto prefetch = [&](int buf, int kc) {
        __half* S = sdyn + buf * GBUF1;
#pragma unroll
        for (int i = 0; i < 2; i++) {
            int r = s_row + i * 64;
            size_t go = (size_t)r * Ksz + kc + s_col8;
            int so = r * GP1 + s_col8;
            cp16(S + so,          A + go);
            cp16(S + PLANE1 + so, B + go);
        }
        cp_commit();
    };

    const int nchunks = Ksz / 32;
    prefetch(0, 0);
    if (nchunks > 1) prefetch(1, 32);

    const int lrow = lane & 7;
    const int lm   = lane >> 3;
    const uint32_t a_off = (uint32_t)(((((lm & 1) * 8) + lrow) * GP1 + (lm >> 1) * 8) * 2);
    const uint32_t b_off = (uint32_t)(((((lm >> 1) * 8) + lrow) * GP1 + (lm & 1) * 8) * 2);

    const uint32_t sbase = (uint32_t)__cvta_generic_to_shared(sdyn);

    int buf = 0;
    for (int t = 0; t < nchunks; t++) {
        if (t < nchunks - 1) cp_wait1(); else cp_wait0();
        __syncthreads();
        // issue next prefetch BEFORE compute (overlaps LSU with mma)
        if (t + 2 < nchunks) prefetch((t + 2) % 3, (t + 2) * 32);

        const uint32_t Ab = sbase + (uint32_t)((buf * GBUF1) * 2);
        const uint32_t Bb = Ab + PLANE1 * 2;

#pragma unroll
        for (int ks = 0; ks < 32; ks += 16) {
            uint32_t ah[2][4];
            ldsm4(ah[0], Ab + (uint32_t)(((m_base)      * GP1 + ks) * 2) + a_off);
            ldsm4(ah[1], Ab + (uint32_t)(((m_base + 16) * GP1 + ks) * 2) + a_off);
            uint32_t bh[4][4];
#pragma unroll
            for (int nbp = 0; nbp < 4; nbp++)
                ldsm4(bh[nbp], Bb + (uint32_t)(((n_base + nbp * 16) * GP1 + ks) * 2) + b_off);
#pragma unroll
            for (int nbp = 0; nbp < 4; nbp++)
#pragma unroll
                for (int mt = 0; mt < 2; mt++) {
                    mma_f16(F.c[mt][2 * nbp],     ah[mt][0], ah[mt][1], ah[mt][2], ah[mt][3],
                            bh[nbp][0], bh[nbp][1]);
                    mma_f16(F.c[mt][2 * nbp + 1], ah[mt][0], ah[mt][1], ah[mt][2], ah[mt][3],
                            bh[nbp][2], bh[nbp][3]);
                }
        }
        buf = (buf == 2) ? 0 : buf + 1;
    }
}

// ===========================================================================
// fp16 GEMM core #2: C[64x128], 8 warps (2m x 4n), K-chunk 32, triple-buffered.
// Used by proj for finer grid granularity (wave-quantization fix).
// ===========================================================================
struct GemmFrag64 {
    float c[2][4][4];
};

__device__ __forceinline__ void gemm64_tile(
    GemmFrag64& F,
    const __half* __restrict__ A, const __half* __restrict__ B,
    int Ksz, __half* sdyn, int m_base, int n_base)
{
    const int tid  = threadIdx.x;
    const int lane = tid & 31;
#pragma unroll
    for (int mt = 0; mt < 2; mt++)
#pragma unroll
        for (int nb = 0; nb < 4; nb++)
#pragma unroll
            for (int j = 0; j < 4; j++) F.c[mt][nb][j] = 0.0f;

    const int s_row  = tid >> 2;             // 0..63
    const int s_col8 = (tid & 3) << 3;

    auto prefetch = [&](int buf, int kc) {
        __half* S = sdyn + buf * GBUF64;
        // A: 64 rows (1 chunk / thread)
        cp16(S + s_row * GP1 + s_col8, A + (size_t)s_row * Ksz + kc + s_col8);
        // B: 128 rows (2 chunks / thread)
#pragma unroll
        for (int i = 0; i < 2; i++) {
            int r = s_row + i * 64;
            cp16(S + PLANE_A64 + r * GP1 + s_col8, B + (size_t)r * Ksz + kc + s_col8);
        }
        cp_commit();
    };

    const int nchunks = Ksz / 32;
    prefetch(0, 0);
    if (nchunks > 1) prefetch(1, 32);

    const int lrow = lane & 7;
    const int lm   = lane >> 3;
    const uint32_t a_off = (uint32_t)(((((lm & 1) * 8) + lrow) * GP1 + (lm >> 1) * 8) * 2);
    const uint32_t b_off = (uint32_t)(((((lm >> 1) * 8) + lrow) * GP1 + (lm & 1) * 8) * 2);

    const uint32_t sbase = (uint32_t)__cvta_generic_to_shared(sdyn);

    int buf = 0;
    for (int t = 0; t < nchunks; t++) {
        if (t < nchunks - 1) cp_wait1(); else cp_wait0();
        __syncthreads();
        if (t + 2 < nchunks) prefetch((t + 2) % 3, (t + 2) * 32);

        const uint32_t Ab = sbase + (uint32_t)((buf * GBUF64) * 2);
        const uint32_t Bb = Ab + PLANE_A64 * 2;

#pragma unroll
        for (int ks = 0; ks < 32; ks += 16) {
            uint32_t ah[2][4];
            ldsm4(ah[0], Ab + (uint32_t)(((m_base)      * GP1 + ks) * 2) + a_off);
            ldsm4(ah[1], Ab + (uint32_t)(((m_base + 16) * GP1 + ks) * 2) + a_off);
            uint32_t bh[2][4];
#pragma unroll
            for (int nbp = 0; nbp < 2; nbp++)
                ldsm4(bh[nbp], Bb + (uint32_t)(((n_base + nbp * 16) * GP1 + ks) * 2) + b_off);
#pragma unroll
            for (int nbp = 0; nbp < 2; nbp++)
#pragma unroll
                for (int mt = 0; mt < 2; mt++) {
                    mma_f16(F.c[mt][2 * nbp],     ah[mt][0], ah[mt][1], ah[mt][2], ah[mt][3],
                            bh[nbp][0], bh[nbp][1]);
                    mma_f16(F.c[mt][2 * nbp + 1], ah[mt][0], ah[mt][1], ah[mt][2], ah[mt][3],
                            bh[nbp][2], bh[nbp][3]);
                }
        }
        buf = (buf == 2) ? 0 : buf + 1;
    }
}

// ---------------------------------------------------------------------------
// Kernel 1: QKV projection. w = blockIdx.y/6 is CTA-uniform.
// ---------------------------------------------------------------------------
__global__ __launch_bounds__(256, 2) void qkv_kernel(const float* __restrict__ bias)
{
    extern __shared__ __half sg[];

    const int tid  = threadIdx.x;
    const int lane = tid & 31;
    const int wid  = tid >> 5;
    const int g    = lane >> 2;
    const int q    = lane & 3;
    const int m_base = (wid & 3) * 32;
    const int n_base = (wid >> 2) * 64;
    const int m0 = blockIdx.x * 128;
    const int n0 = blockIdx.y * 128;
    const int w  = blockIdx.y / 6;
    const int bb = m0 >> 12;
    const int t0 = m0 & (TT - 1);

    GemmFrag F;
    gemm1_tile(F, g_xh + (size_t)m0 * CC, g_wqh + (size_t)n0 * CC,
               CC, sg, m_base, n_base);

    if (w < 2) {
#pragma unroll
        for (int mt = 0; mt < 2; mt++) {
            int row = m0 + m_base + mt * 16 + g;
#pragma unroll
            for (int nb = 0; nb < 8; nb++) {
                int n = n0 + n_base + nb * 8 + 2 * q;
                int r = n - w * CC;
                int h = r >> 6;
                int d = r & 63;
                float bs0 = bias[n], bs1 = bias[n + 1];
#pragma unroll
                for (int half = 0; half < 2; half++) {
                    int t  = (row + half * 8) & (TT - 1);
                    float v0 = F.c[mt][nb][2 * half + 0] + bs0;
                    float v1 = F.c[mt][nb][2 * half + 1] + bs1;
                    size_t bh = (size_t)(bb * HH + h);
                    if (w == 0) {
                        *(__half2*)(g_qh + (bh * TT + t) * DK + d) = __floats2half2_rn(v0, v1);
                    } else {
                        *(__half2*)(g_k + (bh * TT + t) * DK + d) =
                            __floats2half2_rn(v0 * KSCALE, v1 * KSCALE);
                    }
                }
            }
        }
    } else {
        // V: stage [col][tok] transposed in smem, then coalesced rows out
        __syncthreads();
#pragma unroll
        for (int mt = 0; mt < 2; mt++) {
            int trow = m_base + mt * 16 + g;
#pragma unroll
            for (int nb = 0; nb < 8; nb++) {
                int cl = n_base + nb * 8 + 2 * q;
                int n = n0 + cl;
                float bs0 = bias[n], bs1 = bias[n + 1];
#pragma unroll
                for (int half = 0; half < 2; half++) {
                    int tk = trow + half * 8;
                    sg[(cl)     * VTP + tk] =
                        __float2half_rn(F.c[mt][nb][2 * half + 0] + bs0);
                    sg[(cl + 1) * VTP + tk] =
                        __float2half_rn(F.c[mt][nb][2 * half + 1] + bs1);
                }
            }
        }
        __syncthreads();
        const int rowl = tid >> 1;
        const int seg  = tid & 1;
        const int r    = (blockIdx.y - 12) * 128 + rowl;
        const int h    = r >> 6;
        const int d    = r & 63;
        __half* dst = g_vt + ((size_t)(bb * HH + h) * DK + d) * TT + t0 + seg * 64;
        const __half* src = sg + rowl * VTP + seg * 64;
#pragma unroll
        for (int i = 0; i < 8; i++)
            *(uint4*)(dst + i * 8) = *(const uint4*)(src + i * 8);
    }
}

// ---------------------------------------------------------------------------
// Kernel 2: fp16 m16n8k16 flash attention, triple-buffered, distance-2,
// prefetch issued right after the barrier.
// ---------------------------------------------------------------------------
__global__ __launch_bounds__(256, 2) void attn_mma_kernel()
{
    extern __shared__ __half sdyn[];   // [3][ K(64x72) | Vt(64x72) ]

    const int tid  = threadIdx.x;
    const int lane = tid & 31;
    const int w    = tid >> 5;
    const int g    = lane >> 2;
    const int q    = lane & 3;
    const int q0   = blockIdx.x * 128;
    const int bh   = blockIdx.y;
    const int bb   = bh / HH;
    const int h    = bh % HH;

    const __half* qb  = g_qh + (size_t)bh * TT * DK;
    const __half* kb  = g_k  + (size_t)bh * TT * DK;
    const __half* vtb = g_vt + (size_t)bh * DK * TT;

    const uint32_t sbase = (uint32_t)__cvta_generic_to_shared(sdyn);

    const int lrow = lane & 7;
    const int lm   = lane >> 3;
    const uint32_t s_lane = (uint32_t)((lrow * HPITCH + lm * 8) * 2);
    const uint32_t v_lane = (uint32_t)(((((lm >> 1) * 8) + lrow) * HPITCH + (lm & 1) * 8) * 2);

    const int c_row = tid >> 3;
    const int c_col = (tid & 7) << 3;

    auto stage = [&](int buf, int kt) {
        __half* Kb = sdyn + buf * BUF_H;
        __half* Vb = Kb + TILE_H;
#pragma unroll
        for (int i = 0; i < 2; i++) {
            int r = c_row + i * 32;
            cp16(&Kb[r * HPITCH + c_col], kb + (size_t)(kt + r) * DK + c_col);
        }
#pragma unroll
        for (int i = 0; i < 2; i++) {
            int r = c_row + i * 32;
            cp16(&Vb[r * HPITCH + c_col], vtb + (size_t)r * TT + kt + c_col);
        }
        cp_commit();
    };

    stage(0, 0);
    stage(1, 64);

    uint32_t qa[4][4];
    {
        const __half* qr = qb + (size_t)(q0 + w * 16 + g) * DK;
#pragma unroll
        for (int k0 = 0; k0 < 4; k0++) {
            qa[k0][0] = *(const uint32_t*)(qr + k0 * 16 + 2 * q);
            qa[k0][1] = *(const uint32_t*)(qr + 8 * DK + k0 * 16 + 2 * q);
            qa[k0][2] = *(const uint32_t*)(qr + k0 * 16 + 2 * q + 8);
            qa[k0][3] = *(const uint32_t*)(qr + 8 * DK + k0 * 16 + 2 * q + 8);
        }
    }

    float o[8][4];
#pragma unroll
    for (int n = 0; n < 8; n++)
#pragma unroll
        for (int j = 0; j < 4; j++) o[n][j] = 0.0f;
    float rsum0 = 0.0f, rsum1 = 0.0f;

    const int ntiles = TT / 64;
    int buf = 0;
    for (int t = 0; t < ntiles; t++) {
        if (t < ntiles - 1) cp_wait1(); else cp_wait0();
        __syncthreads();
        if (t + 2 < ntiles) stage((t + 2) % 3, (t + 2) * 64);

        const uint32_t Ksb = sbase + (uint32_t)((buf * BUF_H) * 2);
        const uint32_t Vsb = Ksb + TILE_H * 2;

#pragma unroll
        for (int j2 = 0; j2 < 4; j2++) {
            const uint32_t j2k = (uint32_t)(j2 * 16 * HPITCH * 2);
            const uint32_t j2v = (uint32_t)(j2 * 16 * 2);

            uint32_t sb[4][4];
            ldsm4(sb[0], Ksb + j2k + s_lane);
            ldsm4(sb[1], Ksb + j2k + s_lane + 4 * 8 * 2);
            ldsm4(sb[2], Ksb + j2k + s_lane + (uint32_t)(8 * HPITCH * 2));
            ldsm4(sb[3], Ksb + j2k + s_lane + (uint32_t)(8 * HPITCH * 2) + 4 * 8 * 2);

            float sc0[4] = {0.0f, 0.0f, 0.0f, 0.0f};
            float sc1[4] = {0.0f, 0.0f, 0.0f, 0.0f};
            mma_f16(sc0, qa[0][0], qa[0][1], qa[0][2], qa[0][3], sb[0][0], sb[0][1]);
            mma_f16(sc1, qa[0][0], qa[0][1], qa[0][2], qa[0][3], sb[2][0], sb[2][1]);
            mma_f16(sc0, qa[1][0], qa[1][1], qa[1][2], qa[1][3], sb[0][2], sb[0][3]);
            mma_f16(sc1, qa[1][0], qa[1][1], qa[1][2], qa[1][3], sb[2][2], sb[2][3]);
            mma_f16(sc0, qa[2][0], qa[2][1], qa[2][2], qa[2][3], sb[1][0], sb[1][1]);
            mma_f16(sc1, qa[2][0], qa[2][1], qa[2][2], qa[2][3], sb[3][0], sb[3][1]);
            mma_f16(sc0, qa[3][0], qa[3][1], qa[3][2], qa[3][3], sb[1][2], sb[1][3]);
            mma_f16(sc1, qa[3][0], qa[3][1], qa[3][2], qa[3][3], sb[3][2], sb[3][3]);

            uint32_t pa0 = packh2(exp2f(sc0[0]), exp2f(sc0[1]));
            uint32_t pa1 = packh2(exp2f(sc0[2]), exp2f(sc0[3]));
            uint32_t pa2 = packh2(exp2f(sc1[0]), exp2f(sc1[1]));
            uint32_t pa3 = packh2(exp2f(sc1[2]), exp2f(sc1[3]));
            {
                float2 f0 = __half22float2(*(__half2*)&pa0);
                float2 f1 = __half22float2(*(__half2*)&pa1);
                float2 f2 = __half22float2(*(__half2*)&pa2);
                float2 f3 = __half22float2(*(__half2*)&pa3);
                rsum0 += f0.x + f0.y + f2.x + f2.y;
                rsum1 += f1.x + f1.y + f3.x + f3.y;
            }

#pragma unroll
            for (int n = 0; n < 4; n++) {
                uint32_t pb[4];
                ldsm4(pb, Vsb + j2v + v_lane + (uint32_t)(n * 16 * HPITCH * 2));
                mma_f16(o[2 * n],     pa0, pa1, pa2, pa3, pb[0], pb[1]);
                mma_f16(o[2 * n + 1], pa0, pa1, pa2, pa3, pb[2], pb[3]);
            }
        }
        buf = (buf == 2) ? 0 : buf + 1;
    }

    rsum0 += __shfl_xor_sync(0xffffffffu, rsum0, 1);
    rsum0 += __shfl_xor_sync(0xffffffffu, rsum0, 2);
    rsum1 += __shfl_xor_sync(0xffffffffu, rsum1, 1);
    rsum1 += __shfl_xor_sync(0xffffffffu, rsum1, 2);
    const float inv0 = 1.0f / rsum0;
    const float inv1 = 1.0f / rsum1;

    const int r0 = q0 + w * 16 + g;
    const int r1 = r0 + 8;
    const size_t o0 = ((size_t)(bb * TT + r0)) * CC + h * DK;
    const size_t o1 = ((size_t)(bb * TT + r1)) * CC + h * DK;
#pragma unroll
    for (int n0 = 0; n0 < 8; n0++) {
        *(__half2*)(g_ah + o0 + n0 * 8 + 2 * q) =
            __floats2half2_rn(o[n0][0] * inv0, o[n0][1] * inv0);
        *(__half2*)(g_ah + o1 + n0 * 8 + 2 * q) =
            __floats2half2_rn(o[n0][2] * inv1, o[n0][3] * inv1);
    }
}

// ---------------------------------------------------------------------------
// Kernel 3: output projection, 64x128 tiles (wave-quantization fix).
// grid = (M_TOK/64, CC/128) = (128, 6) = 768 CTAs.
// ---------------------------------------------------------------------------
__global__ __launch_bounds__(256, 2) void proj_kernel(
    const float* __restrict__ bias,
    float* __restrict__ out)
{
    extern __shared__ __half sg[];

    const int tid  = threadIdx.x;
    const int lane = tid & 31;
    const int wid  = tid >> 5;
    const int g    = lane >> 2;
    const int q    = lane & 3;
    const int m_base = (wid & 1) * 32;
    const int n_base = (wid >> 1) * 32;
    const int m0 = blockIdx.x * 64;
    const int n0 = blockIdx.y * 128;

    GemmFrag64 F;
    gemm64_tile(F, g_ah + (size_t)m0 * CC, g_woh + (size_t)n0 * CC,
                CC, sg, m_base, n_base);

#pragma unroll
    for (int mt = 0; mt < 2; mt++) {
        int row = m0 + m_base + mt * 16 + g;
#pragma unroll
        for (int nb = 0; nb < 4; nb++) {
            int n = n0 + n_base + nb * 8 + 2 * q;
            float bs0 = bias[n], bs1 = bias[n + 1];
#pragma unroll
            for (int half = 0; half < 2; half++) {
                int m = row + half * 8;
                float2 o;
                o.x = F.c[mt][nb][2 * half + 0] + bs0;
                o.y = F.c[mt][nb][2 * half + 1] + bs1;
                *(float2*)(out + (size_t)m * CC + n) = o;
            }
        }
    }
}

// ---------------------------------------------------------------------------
extern "C" void kernel_launch(void* const* d_in, const int* in_sizes, int n_in,
                              void* d_out, int out_size)
{
    const float* x     = (const float*)d_in[0];
    const float* W_qkv = (const float*)d_in[1];
    const float* b_qkv = (const float*)d_in[2];
    const float* W_out = (const float*)d_in[3];
    const float* b_out = (const float*)d_in[4];
    float* out = (float*)d_out;

    static int attr_set = 0;
    if (!attr_set) {
        cudaFuncSetAttribute(qkv_kernel,
                             cudaFuncAttributeMaxDynamicSharedMemorySize, GEMM_SMEM);
        cudaFuncSetAttribute(proj_kernel,
                             cudaFuncAttributeMaxDynamicSharedMemorySize, GEMM64_SMEM);
        cudaFuncSetAttribute(attn_mma_kernel,
                             cudaFuncAttributeMaxDynamicSharedMemorySize, ATTN_SMEM);
        attr_set = 1;
    }

    prepass_kernel<<<XB + QB + OB, 256>>>(x, W_qkv, W_out);

    dim3 g1(M_TOK / 128, N_QKV / 128);   // 64 x 18
    qkv_kernel<<<g1, 256, GEMM_SMEM>>>(b_qkv);

    dim3 g2(TT / 128, BB * HH);          // 32 x 24
    attn_mma_kernel<<<g2, 256, ATTN_SMEM>>>();

    dim3 g3(M_TOK / 64, CC / 128);       // 128 x 6
    proj_kernel<<<g3, 256, GEMM64_SMEM>>>(b_out, out);
}

// round 16
// speedup vs baseline: 1.0165x; 1.0165x over previous
#include <cuda_runtime.h>
#include <cuda_fp16.h>
#include <cstdint>

#define BB 2
#define TT 4096
#define CC 768
#define HH 12
#define DK 64
#define M_TOK (BB*TT)      // 8192
#define N_QKV (3*CC)       // 2304

// attn fp16 tiles: 64 rows x 72-half pitch, TRIPLE buffered
#define HPITCH 72
#define TILE_H (64*HPITCH)
#define BUF_H  (2*TILE_H)             // K + Vt per buffer (9216 halves)
#define ATTN_SMEM (3*BUF_H*2)         // 55296 bytes

// fp16 GEMM smem: 2 planes (A,B) x 128 rows x 56-half pitch, K-chunk 48, TRIPLE buffered
#define GPQ 56
#define PLANEQ (128*GPQ)              // 7168 halves
#define GBUFQ  (2*PLANEQ)             // 14336 halves per buffer
#define GEMM_SMEM (3*GBUFQ*2)         // 86016 bytes

// V-transpose staging pitch (halves): 136 -> 272B rows, 16B-aligned uint4 reads
#define VTP 136

// K pre-scale: (1/8) * log2(e)
#define KSCALE 0.180336879f

// Scratch (allocation-free rule: __device__ globals)
__device__ __half g_qh [(size_t)BB*HH*TT*DK];
__device__ __half g_k  [(size_t)BB*HH*TT*DK];
__device__ __half g_vt [(size_t)BB*HH*DK*TT];
__device__ __half g_ah [(size_t)BB*TT*CC];
__device__ __half g_xh [(size_t)M_TOK*CC];
__device__ __half g_wqh[(size_t)N_QKV*CC];
__device__ __half g_woh[(size_t)CC*CC];

__device__ __forceinline__ uint32_t packh2(float lo, float hi) {
    __half2 h = __floats2half2_rn(lo, hi);
    return *(uint32_t*)&h;
}

__device__ __forceinline__ void mma_f16(float c[4],
                                        uint32_t a0, uint32_t a1, uint32_t a2, uint32_t a3,
                                        uint32_t b0, uint32_t b1) {
    asm volatile(
        "mma.sync.aligned.m16n8k16.row.col.f32.f16.f16.f32 "
        "{%0,%1,%2,%3}, {%4,%5,%6,%7}, {%8,%9}, {%0,%1,%2,%3};"
        : "+f"(c[0]), "+f"(c[1]), "+f"(c[2]), "+f"(c[3])
        : "r"(a0), "r"(a1), "r"(a2), "r"(a3), "r"(b0), "r"(b1));
}

__device__ __forceinline__ void ldsm4(uint32_t r[4], uint32_t saddr) {
    asm volatile("ldmatrix.sync.aligned.m8n8.x4.shared.b16 {%0,%1,%2,%3}, [%4];"
        : "=r"(r[0]), "=r"(r[1]), "=r"(r[2]), "=r"(r[3]) : "r"(saddr));
}

__device__ __forceinline__ void cp16(void* dst_smem, const void* src) {
    uint32_t d = (uint32_t)__cvta_generic_to_shared(dst_smem);
    asm volatile("cp.async.cg.shared.global [%0], [%1], 16;" :: "r"(d), "l"(src));
}
__device__ __forceinline__ void cp_commit() {
    asm volatile("cp.async.commit_group;");
}
__device__ __forceinline__ void cp_wait1() { asm volatile("cp.async.wait_group 1;"); }
__device__ __forceinline__ void cp_wait0() { asm volatile("cp.async.wait_group 0;"); }

// ---------------------------------------------------------------------------
// Merged prepass: block-range dispatch.
// ---------------------------------------------------------------------------
#define XB (M_TOK*CC/1024)        // 6144
#define QB ((N_QKV/32)*(CC/32))   // 1728
#define OB ((CC/32)*(CC/32))      // 576

__global__ __launch_bounds__(256) void prepass_kernel(
    const float* __restrict__ x,
    const float* __restrict__ Wq,
    const float* __restrict__ Wo)
{
    __shared__ float ts[32][33];
    const int b   = blockIdx.x;
    const int tid = threadIdx.x;

    if (b < XB) {
        size_t base = ((size_t)b * 256 + tid) * 4;
        float4 v = *(const float4*)(x + base);
        *(__half2*)(g_xh + base)     = __floats2half2_rn(v.x, v.y);
        *(__half2*)(g_xh + base + 2) = __floats2half2_rn(v.z, v.w);
        return;
    }

    const float* W;
    __half* T;
    int K, N, bx, by;
    if (b < XB + QB) {
        int bb2 = b - XB;
        W = Wq; T = g_wqh; K = CC; N = N_QKV;
        bx = bb2 % (N_QKV / 32); by = bb2 / (N_QKV / 32);
    } else {
        int bb2 = b - XB - QB;
        W = Wo; T = g_woh; K = CC; N = CC;
        bx = bb2 % (CC / 32); by = bb2 / (CC / 32);
    }
    const int tx = tid & 31, ty = tid >> 5;           // 32 x 8
    const int n0 = bx * 32, k0 = by * 32;
#pragma unroll
    for (int i = 0; i < 32; i += 8)
        ts[ty + i][tx] = W[(size_t)(k0 + ty + i) * N + n0 + tx];
    __syncthreads();
#pragma unroll
    for (int i = 0; i < 32; i += 8)
        T[(size_t)(n0 + ty + i) * K + k0 + tx] = __float2half_rn(ts[tx][ty + i]);
}

// ===========================================================================
// fp16 GEMM core: C[128x128], 8 warps (4m x 2n), K-chunk 48, triple-buffered,
// distance-2 prefetch issued AFTER compute (trailing placement).
// ===========================================================================
struct GemmFrag {
    float c[2][8][4];
};

__device__ __forceinline__ void gemm1_tile(
    GemmFrag& F,
    const __half* __restrict__ A, const __half* __restrict__ B,
    int Ksz, __half* sdyn, int m_base, int n_base)
{
    const int tid  = threadIdx.x;
    const int lane = tid & 31;
#pragma unroll
    for (int mt = 0; mt < 2; mt++)
#pragma unroll
        for (int nb = 0; nb < 8; nb++)
#pragma unroll
            for (int j = 0; j < 4; j++) F.c[mt][nb][j] = 0.0f;

    // cp.async mapping: 768 16B-chunks per plane (128 rows x 6), 3 per thread
    int p_row[3], p_col[3];
#pragma unroll
    for (int i = 0; i < 3; i++) {
        int idx = tid + i * 256;
        p_row[i] = idx / 6;
        p_col[i] = (idx % 6) * 8;
    }

    auto prefetch = [&](int buf, int kc) {
        __half* S = sdyn + buf * GBUFQ;
#pragma unroll
        for (int i = 0; i < 3; i++) {
            size_t go = (size_t)p_row[i] * Ksz + kc + p_col[i];
            int so = p_row[i] * GPQ + p_col[i];
            cp16(S + so,          A + go);
            cp16(S + PLANEQ + so, B + go);
        }
        cp_commit();
    };

    const int nchunks = Ksz / 48;
    prefetch(0, 0);
    if (nchunks > 1) prefetch(1, 48);

    const int lrow = lane & 7;
    const int lm   = lane >> 3;
    const uint32_t a_off = (uint32_t)(((((lm & 1) * 8) + lrow) * GPQ + (lm >> 1) * 8) * 2);
    const uint32_t b_off = (uint32_t)(((((lm >> 1) * 8) + lrow) * GPQ + (lm & 1) * 8) * 2);

    const uint32_t sbase = (uint32_t)__cvta_generic_to_shared(sdyn);

    int buf = 0;
    for (int t = 0; t < nchunks; t++) {
        if (t < nchunks - 1) cp_wait1(); else cp_wait0();
        __syncthreads();

        const uint32_t Ab = sbase + (uint32_t)((buf * GBUFQ) * 2);
        const uint32_t Bb = Ab + PLANEQ * 2;

#pragma unroll
        for (int ks = 0; ks < 48; ks += 16) {
            uint32_t ah[2][4];
            ldsm4(ah[0], Ab + (uint32_t)(((m_base)      * GPQ + ks) * 2) + a_off);
            ldsm4(ah[1], Ab + (uint32_t)(((m_base + 16) * GPQ + ks) * 2) + a_off);
            uint32_t bh[4][4];
#pragma unroll
            for (int nbp = 0; nbp < 4; nbp++)
                ldsm4(bh[nbp], Bb + (uint32_t)(((n_base + nbp * 16) * GPQ + ks) * 2) + b_off);
#pragma unroll
            for (int nbp = 0; nbp < 4; nbp++)
#pragma unroll
                for (int mt = 0; mt < 2; mt++) {
                    mma_f16(F.c[mt][2 * nbp],     ah[mt][0], ah[mt][1], ah[mt][2], ah[mt][3],
                            bh[nbp][0], bh[nbp][1]);
                    mma_f16(F.c[mt][2 * nbp + 1], ah[mt][0], ah[mt][1], ah[mt][2], ah[mt][3],
                            bh[nbp][2], bh[nbp][3]);
                }
        }
        // trailing distance-2 prefetch (R14 placement)
        if (t + 2 < nchunks) prefetch((t + 2) % 3, (t + 2) * 48);
        buf = (buf == 2) ? 0 : buf + 1;
    }
}

// ---------------------------------------------------------------------------
// Kernel 1: QKV projection. w = blockIdx.y/6 is CTA-uniform.
// w==2 (V): transpose through smem, coalesced STG.128 into g_vt.
// ---------------------------------------------------------------------------
__global__ __launch_bounds__(256, 2) void qkv_kernel(const float* __restrict__ bias)
{
    extern __shared__ __half sg[];

    const int tid  = threadIdx.x;
    const int lane = tid & 31;
    const int wid  = tid >> 5;
    const int g    = lane >> 2;
    const int q    = lane & 3;
    const int m_base = (wid & 3) * 32;
    const int n_base = (wid >> 2) * 64;
    const int m0 = blockIdx.x * 128;
    const int n0 = blockIdx.y * 128;
    const int w  = blockIdx.y / 6;          // 0=Q 1=K 2=V (uniform per CTA)
    const int bb = m0 >> 12;
    const int t0 = m0 & (TT - 1);

    GemmFrag F;
    gemm1_tile(F, g_xh + (size_t)m0 * CC, g_wqh + (size_t)n0 * CC,
               CC, sg, m_base, n_base);

    if (w < 2) {
#pragma unroll
        for (int mt = 0; mt < 2; mt++) {
            int row = m0 + m_base + mt * 16 + g;
#pragma unroll
            for (int nb = 0; nb < 8; nb++) {
                int n = n0 + n_base + nb * 8 + 2 * q;
                int r = n - w * CC;
                int h = r >> 6;
                int d = r & 63;
                float bs0 = bias[n], bs1 = bias[n + 1];
#pragma unroll
                for (int half = 0; half < 2; half++) {
                    int t  = (row + half * 8) & (TT - 1);
                    float v0 = F.c[mt][nb][2 * half + 0] + bs0;
                    float v1 = F.c[mt][nb][2 * half + 1] + bs1;
                    size_t bh = (size_t)(bb * HH + h);
                    if (w == 0) {
                        *(__half2*)(g_qh + (bh * TT + t) * DK + d) = __floats2half2_rn(v0, v1);
                    } else {
                        *(__half2*)(g_k + (bh * TT + t) * DK + d) =
                            __floats2half2_rn(v0 * KSCALE, v1 * KSCALE);
                    }
                }
            }
        }
    } else {
        // V: stage [col][tok] transposed in smem, then coalesced rows out
        __syncthreads();    // all warps done reading GEMM buffers
#pragma unroll
        for (int mt = 0; mt < 2; mt++) {
            int trow = m_base + mt * 16 + g;
#pragma unroll
            for (int nb = 0; nb < 8; nb++) {
                int cl = n_base + nb * 8 + 2 * q;
                int n = n0 + cl;
                float bs0 = bias[n], bs1 = bias[n + 1];
#pragma unroll
                for (int half = 0; half < 2; half++) {
                    int tk = trow + half * 8;
                    sg[(cl)     * VTP + tk] =
                        __float2half_rn(F.c[mt][nb][2 * half + 0] + bs0);
                    sg[(cl + 1) * VTP + tk] =
                        __float2half_rn(F.c[mt][nb][2 * half + 1] + bs1);
                }
            }
        }
        __syncthreads();
        const int rowl = tid >> 1;
        const int seg  = tid & 1;
        const int r    = (blockIdx.y - 12) * 128 + rowl;   // 0..767
        const int h    = r >> 6;
        const int d    = r & 63;
        __half* dst = g_vt + ((size_t)(bb * HH + h) * DK + d) * TT + t0 + seg * 64;
        const __half* src = sg + rowl * VTP + seg * 64;
#pragma unroll
        for (int i = 0; i < 8; i++)
            *(uint4*)(dst + i * 8) = *(const uint4*)(src + i * 8);
    }
}

// ---------------------------------------------------------------------------
// Kernel 2: fp16 m16n8k16 flash attention, triple-buffered, distance-2,
// trailing prefetch placement (R14).
// ---------------------------------------------------------------------------
__global__ __launch_bounds__(256, 2) void attn_mma_kernel()
{
    extern __shared__ __half sdyn[];   // [3][ K(64x72) | Vt(64x72) ]

    const int tid  = threadIdx.x;
    const int lane = tid & 31;
    const int w    = tid >> 5;
    const int g    = lane >> 2;
    const int q    = lane & 3;
    const int q0   = blockIdx.x * 128;
    const int bh   = blockIdx.y;
    const int bb   = bh / HH;
    const int h    = bh % HH;

    const __half* qb  = g_qh + (size_t)bh * TT * DK;
    const __half* kb  = g_k  + (size_t)bh * TT * DK;
    const __half* vtb = g_vt + (size_t)bh * DK * TT;

    const uint32_t sbase = (uint32_t)__cvta_generic_to_shared(sdyn);

    const int lrow = lane & 7;
    const int lm   = lane >> 3;
    const uint32_t s_lane = (uint32_t)((lrow * HPITCH + lm * 8) * 2);
    const uint32_t v_lane = (uint32_t)(((((lm >> 1) * 8) + lrow) * HPITCH + (lm & 1) * 8) * 2);

    const int c_row = tid >> 3;
    const int c_col = (tid & 7) << 3;

    auto stage = [&](int buf, int kt) {
        __half* Kb = sdyn + buf * BUF_H;
        __half* Vb = Kb + TILE_H;
#pragma unroll
        for (int i = 0; i < 2; i++) {
            int r = c_row + i * 32;
            cp16(&Kb[r * HPITCH + c_col], kb + (size_t)(kt + r) * DK + c_col);
        }
#pragma unroll
        for (int i = 0; i < 2; i++) {
            int r = c_row + i * 32;
            cp16(&Vb[r * HPITCH + c_col], vtb + (size_t)r * TT + kt + c_col);
        }
        cp_commit();
    };

    stage(0, 0);
    stage(1, 64);

    uint32_t qa[4][4];
    {
        const __half* qr = qb + (size_t)(q0 + w * 16 + g) * DK;
#pragma unroll
        for (int k0 = 0; k0 < 4; k0++) {
            qa[k0][0] = *(const uint32_t*)(qr + k0 * 16 + 2 * q);
            qa[k0][1] = *(const uint32_t*)(qr + 8 * DK + k0 * 16 + 2 * q);
            qa[k0][2] = *(const uint32_t*)(qr + k0 * 16 + 2 * q + 8);
            qa[k0][3] = *(const uint32_t*)(qr + 8 * DK + k0 * 16 + 2 * q + 8);
        }
    }

    float o[8][4];
#pragma unroll
    for (int n = 0; n < 8; n++)
#pragma unroll
        for (int j = 0; j < 4; j++) o[n][j] = 0.0f;
    float rsum0 = 0.0f, rsum1 = 0.0f;

    const int ntiles = TT / 64;
    int buf = 0;
    for (int t = 0; t < ntiles; t++) {
        if (t < ntiles - 1) cp_wait1(); else cp_wait0();
        __syncthreads();

        const uint32_t Ksb = sbase + (uint32_t)((buf * BUF_H) * 2);
        const uint32_t Vsb = Ksb + TILE_H * 2;

#pragma unroll
        for (int j2 = 0; j2 < 4; j2++) {
            const uint32_t j2k = (uint32_t)(j2 * 16 * HPITCH * 2);
            const uint32_t j2v = (uint32_t)(j2 * 16 * 2);

            uint32_t sb[4][4];
            ldsm4(sb[0], Ksb + j2k + s_lane);
            ldsm4(sb[1], Ksb + j2k + s_lane + 4 * 8 * 2);
            ldsm4(sb[2], Ksb + j2k + s_lane + (uint32_t)(8 * HPITCH * 2));
            ldsm4(sb[3], Ksb + j2k + s_lane + (uint32_t)(8 * HPITCH * 2) + 4 * 8 * 2);

            float sc0[4] = {0.0f, 0.0f, 0.0f, 0.0f};
            float sc1[4] = {0.0f, 0.0f, 0.0f, 0.0f};
            mma_f16(sc0, qa[0][0], qa[0][1], qa[0][2], qa[0][3], sb[0][0], sb[0][1]);
            mma_f16(sc1, qa[0][0], qa[0][1], qa[0][2], qa[0][3], sb[2][0], sb[2][1]);
            mma_f16(sc0, qa[1][0], qa[1][1], qa[1][2], qa[1][3], sb[0][2], sb[0][3]);
            mma_f16(sc1, qa[1][0], qa[1][1], qa[1][2], qa[1][3], sb[2][2], sb[2][3]);
            mma_f16(sc0, qa[2][0], qa[2][1], qa[2][2], qa[2][3], sb[1][0], sb[1][1]);
            mma_f16(sc1, qa[2][0], qa[2][1], qa[2][2], qa[2][3], sb[3][0], sb[3][1]);
            mma_f16(sc0, qa[3][0], qa[3][1], qa[3][2], qa[3][3], sb[1][2], sb[1][3]);
            mma_f16(sc1, qa[3][0], qa[3][1], qa[3][2], qa[3][3], sb[3][2], sb[3][3]);

            uint32_t pa0 = packh2(exp2f(sc0[0]), exp2f(sc0[1]));
            uint32_t pa1 = packh2(exp2f(sc0[2]), exp2f(sc0[3]));
            uint32_t pa2 = packh2(exp2f(sc1[0]), exp2f(sc1[1]));
            uint32_t pa3 = packh2(exp2f(sc1[2]), exp2f(sc1[3]));
            {
                float2 f0 = __half22float2(*(__half2*)&pa0);
                float2 f1 = __half22float2(*(__half2*)&pa1);
                float2 f2 = __half22float2(*(__half2*)&pa2);
                float2 f3 = __half22float2(*(__half2*)&pa3);
                rsum0 += f0.x + f0.y + f2.x + f2.y;
                rsum1 += f1.x + f1.y + f3.x + f3.y;
            }

#pragma unroll
            for (int n = 0; n < 4; n++) {
                uint32_t pb[4];
                ldsm4(pb, Vsb + j2v + v_lane + (uint32_t)(n * 16 * HPITCH * 2));
                mma_f16(o[2 * n],     pa0, pa1, pa2, pa3, pb[0], pb[1]);
                mma_f16(o[2 * n + 1], pa0, pa1, pa2, pa3, pb[2], pb[3]);
            }
        }
        if (t + 2 < ntiles) stage((t + 2) % 3, (t + 2) * 64);
        buf = (buf == 2) ? 0 : buf + 1;
    }

    rsum0 += __shfl_xor_sync(0xffffffffu, rsum0, 1);
    rsum0 += __shfl_xor_sync(0xffffffffu, rsum0, 2);
    rsum1 += __shfl_xor_sync(0xffffffffu, rsum1, 1);
    rsum1 += __shfl_xor_sync(0xffffffffu, rsum1, 2);
    const float inv0 = 1.0f / rsum0;
    const float inv1 = 1.0f / rsum1;

    const int r0 = q0 + w * 16 + g;
    const int r1 = r0 + 8;
    const size_t o0 = ((size_t)(bb * TT + r0)) * CC + h * DK;
    const size_t o1 = ((size_t)(bb * TT + r1)) * CC + h * DK;
#pragma unroll
    for (int n0 = 0; n0 < 8; n0++) {
        *(__half2*)(g_ah + o0 + n0 * 8 + 2 * q) =
            __floats2half2_rn(o[n0][0] * inv0, o[n0][1] * inv0);
        *(__half2*)(g_ah + o1 + n0 * 8 + 2 * q) =
            __floats2half2_rn(o[n0][2] * inv1, o[n0][3] * inv1);
    }
}

// ---------------------------------------------------------------------------
// Kernel 3: output projection, 128x128 tiles (R14 config)
// ---------------------------------------------------------------------------
__global__ __launch_bounds__(256, 2) void proj_kernel(
    const float* __restrict__ bias,
    float* __restrict__ out)
{
    extern __shared__ __half sg[];

    const int tid  = threadIdx.x;
    const int lane = tid & 31;
    const int wid  = tid >> 5;
    const int g    = lane >> 2;
    const int q    = lane & 3;
    const int m_base = (wid & 3) * 32;
    const int n_base = (wid >> 2) * 64;
    const int m0 = blockIdx.x * 128;
    const int n0 = blockIdx.y * 128;

    GemmFrag F;
    gemm1_tile(F, g_ah + (size_t)m0 * CC, g_woh + (size_t)n0 * CC,
               CC, sg, m_base, n_base);

#pragma unroll
    for (int mt = 0; mt < 2; mt++) {
        int row = m0 + m_base + mt * 16 + g;
#pragma unroll
        for (int nb = 0; nb < 8; nb++) {
            int n = n0 + n_base + nb * 8 + 2 * q;
            float bs0 = bias[n], bs1 = bias[n + 1];
#pragma unroll
            for (int half = 0; half < 2; half++) {
                int m = row + half * 8;
                float2 o;
                o.x = F.c[mt][nb][2 * half + 0] + bs0;
                o.y = F.c[mt][nb][2 * half + 1] + bs1;
                *(float2*)(out + (size_t)m * CC + n) = o;
            }
        }
    }
}

// ---------------------------------------------------------------------------
extern "C" void kernel_launch(void* const* d_in, const int* in_sizes, int n_in,
                              void* d_out, int out_size)
{
    const float* x     = (const float*)d_in[0];
    const float* W_qkv = (const float*)d_in[1];
    const float* b_qkv = (const float*)d_in[2];
    const float* W_out = (const float*)d_in[3];
    const float* b_out = (const float*)d_in[4];
    float* out = (float*)d_out;

    static int attr_set = 0;
    if (!attr_set) {
        cudaFuncSetAttribute(qkv_kernel,
                             cudaFuncAttributeMaxDynamicSharedMemorySize, GEMM_SMEM);
        cudaFuncSetAttribute(proj_kernel,
                             cudaFuncAttributeMaxDynamicSharedMemorySize, GEMM_SMEM);
        cudaFuncSetAttribute(attn_mma_kernel,
                             cudaFuncAttributeMaxDynamicSharedMemorySize, ATTN_SMEM);
        attr_set = 1;
    }

    prepass_kernel<<<XB + QB + OB, 256>>>(x, W_qkv, W_out);

    dim3 g1(M_TOK / 128, N_QKV / 128);   // 64 x 18
    qkv_kernel<<<g1, 256, GEMM_SMEM>>>(b_qkv);

    dim3 g2(TT / 128, BB * HH);          // 32 x 24
    attn_mma_kernel<<<g2, 256, ATTN_SMEM>>>();

    dim3 g3(M_TOK / 128, CC / 128);      // 64 x 6
    proj_kernel<<<g3, 256, GEMM_SMEM>>>(b_out, out);
}